// round 2
// baseline (speedup 1.0000x reference)
#include <cuda_runtime.h>
#include <math.h>

#define NC   2000   // codes
#define EV   32     // visits
#define DD   128    // embedding dim
#define HD   256    // hidden dim
#define NOUT 1000
#define NB   16     // batch
#define PAD  128    // max nnz per adj row/col
#define VCAP 128    // max codes per visit
#define NCHUNK 40   // CSC build chunks (40 x 50 rows)
#define CHROWS 50
#define PCH  8      // pool partial chunks
#define EPSF 1e-12f

// ---------------- scratch (device globals; no allocation) ----------------
static __device__ float d_icd[NC*DD];
static __device__ float d_buf[NC*DD];
static __device__ float d_EWh[NC*HD];
static __device__ float d_EWc[NC*HD];
static __device__ float d_IWi[NC*HD];

static __device__ int   d_rowcnt[NC];
static __device__ int   d_rowidx[NC*PAD];
static __device__ int   d_colcnt[NC];
static __device__ int   d_colidx[NC*PAD];
static __device__ int   d_coff[NCHUNK*NC];

static __device__ unsigned d_vmask[NB*NC];
static __device__ unsigned d_smask[NB*NC];
static __device__ unsigned d_dmask[NB*NC];
static __device__ float d_Dv[NB*NC];
static __device__ float d_Dvinv[NB*NC];
static __device__ int d_act[NB*NC];  static __device__ int d_actn[NB];
static __device__ int d_Sl[NB*NC];   static __device__ int d_Sn[NB];
static __device__ int d_Tl[NB*NC];   static __device__ int d_Tn[NB];
static __device__ int d_vl[NB*EV*VCAP];
static __device__ int d_vlen[NB*EV];
static __device__ float d_rowsum[NB*NC];
static __device__ float d_colsum[NB*NC];
static __device__ float d_tph[NB*EV*HD];
static __device__ float d_tpi[NB*EV*HD];
static __device__ float d_yw[(size_t)NB*NC*HD];  // A @ (emb@W_c), rows by S-position
static __device__ float d_zr[(size_t)NB*NC*HD];  // relu(A^T @ yw + b_c), rows by T-position
static __device__ float d_pp[NB*PCH*3*HD];
static __device__ float d_eh[NB*HD], d_ec[NB*HD], d_ei[NB*HD];
static __device__ float d_res[NB*HD];

__device__ __forceinline__ float warp_sum(float v){
  #pragma unroll
  for (int o=16;o>0;o>>=1) v += __shfl_down_sync(0xffffffffu, v, o);
  return v;
}

// ---------------- CSR of adj (warp per row, deterministic ascending) ----------
__global__ void k_csr_rows(const float* __restrict__ adj){
  int w = threadIdx.x >> 5, lane = threadIdx.x & 31;
  int r = blockIdx.x*32 + w;
  if (r >= NC) return;
  int cnt = 0;
  for (int jt=0; jt<NC; jt+=32){
    int j = jt + lane;
    float v = (j < NC) ? adj[(size_t)r*NC + j] : 0.f;
    unsigned m = __ballot_sync(0xffffffffu, v != 0.f);
    if (v != 0.f){
      int pos = cnt + __popc(m & ((1u<<lane)-1u));
      if (pos < PAD) d_rowidx[r*PAD+pos] = j;
    }
    cnt += __popc(m);
  }
  if (lane == 0) d_rowcnt[r] = (cnt < PAD) ? cnt : PAD;
}

// ---------------- CSC build: 3-phase deterministic chunked --------------------
__global__ void kA_colcount(const float* __restrict__ adj){
  int j = blockIdx.y*blockDim.x + threadIdx.x;
  if (j >= NC) return;
  int c = blockIdx.x;
  int cnt = 0;
  int i0 = c*CHROWS;
  for (int i=i0; i<i0+CHROWS; i++)
    if (adj[(size_t)i*NC + j] != 0.f) cnt++;
  d_coff[c*NC + j] = cnt;
}
__global__ void kB_colprefix(){
  int j = blockIdx.x*blockDim.x + threadIdx.x;
  if (j >= NC) return;
  int run = 0;
  for (int c=0; c<NCHUNK; c++){
    int v = d_coff[c*NC + j];
    d_coff[c*NC + j] = run;
    run += v;
  }
  d_colcnt[j] = (run < PAD) ? run : PAD;
}
__global__ void kC_colfill(const float* __restrict__ adj){
  int j = blockIdx.y*blockDim.x + threadIdx.x;
  if (j >= NC) return;
  int c = blockIdx.x;
  int pos = d_coff[c*NC + j];
  int i0 = c*CHROWS;
  for (int i=i0; i<i0+CHROWS; i++){
    if (adj[(size_t)i*NC + j] != 0.f){
      if (pos < PAD) d_colidx[j*PAD + pos] = i;
      pos++;
    }
  }
}

// ---------------- sparse y = adj @ x (binary adj -> plain gather-sum) -----------
__global__ void k_spmm_rows(const float* __restrict__ emb, int use_icd){
  const float* src = use_icd ? d_icd : emb;
  int i = blockIdx.x, d = threadIdx.x;
  int cnt = d_rowcnt[i];
  const int* idx = d_rowidx + i*PAD;
  float acc = 0.f;
  for (int p=0; p<cnt; p++) acc += src[(size_t)idx[p]*DD + d];
  d_buf[i*DD + d] = acc;
}

// ---------------- x = LN(adj.T @ buf) -------------------------------------------
__global__ void k_spmm_cols_ln(const float* __restrict__ g, const float* __restrict__ b){
  int j = blockIdx.x, d = threadIdx.x;
  int cnt = d_colcnt[j];
  const int* idx = d_colidx + j*PAD;
  float acc = 0.f;
  for (int p=0; p<cnt; p++) acc += d_buf[(size_t)idx[p]*DD + d];
  __shared__ float sred[DD];
  sred[d] = acc; __syncthreads();
  for (int s=DD/2; s>0; s>>=1){ if (d < s) sred[d] += sred[d+s]; __syncthreads(); }
  float m = sred[0]/(float)DD; __syncthreads();
  float diff = acc - m;
  sred[d] = diff*diff; __syncthreads();
  for (int s=DD/2; s>0; s>>=1){ if (d < s) sred[d] += sred[d+s]; __syncthreads(); }
  float var = sred[0]/(float)DD;
  d_icd[j*DD + d] = diff*rsqrtf(var + 1e-5f)*g[d] + b[d];
}

// ---------------- EW = X @ W (tiled, 16 rows per block) --------------------------
__global__ void k_gemm(const float* __restrict__ Xin, const float* __restrict__ W, int which){
  const float* X = (which == 2) ? d_icd : Xin;
  float* O = (which == 0) ? d_EWh : (which == 1) ? d_EWc : d_IWi;
  __shared__ float xs[16][DD];
  int r0 = blockIdx.x*16;
  for (int t=threadIdx.x; t<16*DD; t+=256)
    xs[t/DD][t%DD] = X[(size_t)(r0 + t/DD)*DD + (t%DD)];
  __syncthreads();
  float acc[16];
  #pragma unroll
  for (int r=0;r<16;r++) acc[r]=0.f;
  for (int k=0; k<DD; k++){
    float w = W[(size_t)k*HD + threadIdx.x];
    #pragma unroll
    for (int r=0;r<16;r++) acc[r] += xs[r][k]*w;
  }
  #pragma unroll
  for (int r=0;r<16;r++) O[(size_t)(r0+r)*HD + threadIdx.x] = acc[r];
}

// ---------------- per-patient masks / degrees (parallel over code chunks) -------
__global__ void k_masks(const float* __restrict__ cx, const int* __restrict__ lens){
  int b = blockIdx.x;
  int i = blockIdx.y*blockDim.x + threadIdx.x;
  if (i >= NC) return;
  int len = lens[b];
  const float* cxb = cx + (size_t)b*EV*NC;
  unsigned m = 0; int c = 0;
  for (int e=0; e<len; e++){
    if (cxb[(size_t)e*NC + i] != 0.f){ m |= (1u<<e); c++; }
  }
  d_vmask[b*NC+i] = m;
  d_Dv[b*NC+i]    = (float)c;
  d_Dvinv[b*NC+i] = rsqrtf(fmaxf((float)c, EPSF));
  unsigned lowm = (1u << (len-1)) - 1u;
  d_smask[b*NC+i] = m & lowm;
  d_dmask[b*NC+i] = (m >> 1) & lowm;
  d_colsum[b*NC+i] = 0.f;
}

// ---------------- compact lists: per-visit (32 warps) + act/S/T (3 warps) -------
__global__ void k_compact(){
  int b = blockIdx.x;
  int w = threadIdx.x >> 5, lane = threadIdx.x & 31;
  unsigned ltm = (1u<<lane)-1u;
  // per-visit code lists: warp w handles visit w
  {
    int cnt = 0;
    for (int base=0; base<NC; base+=32){
      int i = base + lane;
      bool v = (i<NC) && ((d_vmask[b*NC+i] >> w) & 1u);
      unsigned mm = __ballot_sync(0xffffffffu, v);
      if (v){
        int pos = cnt + __popc(mm & ltm);
        if (pos < VCAP) d_vl[((size_t)b*EV + w)*VCAP + pos] = i;
      }
      cnt += __popc(mm);
    }
    if (lane == 0) d_vlen[b*EV + w] = (cnt < VCAP) ? cnt : VCAP;
  }
  // act / S / T compactions on warps 0..2
  if (w < 3){
    int cnt = 0;
    int* dst = (w==0) ? (d_act + b*NC) : (w==1) ? (d_Sl + b*NC) : (d_Tl + b*NC);
    for (int base=0; base<NC; base+=32){
      int i = base + lane;
      bool v;
      if (w==0)      v = (i<NC) && (d_Dv[b*NC+i] > 0.f);
      else if (w==1) v = (i<NC) && (d_smask[b*NC+i] != 0u);
      else           v = (i<NC) && (d_dmask[b*NC+i] != 0u);
      unsigned mm = __ballot_sync(0xffffffffu, v);
      if (v) dst[cnt + __popc(mm & ltm)] = i;
      cnt += __popc(mm);
    }
    if (lane == 0){
      if (w==0) d_actn[b]=cnt; else if (w==1) d_Sn[b]=cnt; else d_Tn[b]=cnt;
    }
  }
}

// -------- t'[e] = invDe * sum_{i in visit e} Dvinv_i * (X@W)[i] -------------------
__global__ void k_tprime(){
  int b = blockIdx.x, e = blockIdx.y, d = threadIdx.x;
  int n = d_vlen[b*EV + e];
  const int* vl = d_vl + ((size_t)b*EV + e)*VCAP;
  float acch = 0.f, acci = 0.f;
  for (int k=0; k<n; k++){
    int i = vl[k];
    float w = d_Dvinv[b*NC+i];
    acch += w * d_EWh[(size_t)i*HD + d];
    acci += w * d_IWi[(size_t)i*HD + d];
  }
  float inv = 1.f / fmaxf((float)n, EPSF);
  d_tph[((size_t)b*EV+e)*HD + d] = acch*inv;
  d_tpi[((size_t)b*EV+e)*HD + d] = acci*inv;
}

// -------- row/col degree sums of binary transition matrix A ----------------------
__global__ void k_rowcol(){
  __shared__ int      sTi[NC];
  __shared__ unsigned sTd[NC];
  int b = blockIdx.x;
  int Tn = d_Tn[b], Sn = d_Sn[b];
  for (int q=threadIdx.x; q<Tn; q+=blockDim.x){
    int j = d_Tl[b*NC+q];
    sTi[q] = j; sTd[q] = d_dmask[b*NC+j];
  }
  __syncthreads();
  for (int p = blockIdx.y*blockDim.x + threadIdx.x; p < Sn; p += gridDim.y*blockDim.x){
    int i = d_Sl[b*NC+p];
    unsigned sm = d_smask[b*NC+i];
    float rs = 0.f;
    for (int q=0; q<Tn; q++){
      if ((sm & sTd[q]) && sTi[q] != i){
        rs += 1.f;
        atomicAdd(&d_colsum[b*NC + sTi[q]], 1.f);  // exact ints -> deterministic
      }
    }
    d_rowsum[b*NC+i] = rs;
  }
}

// -------- pass1 (4 S-rows/block): yw[i] = rinv_i * sum_j cinv_j * EWc[j] ---------
__global__ void k_pass1(){
  __shared__ int      sTi[NC];
  __shared__ unsigned sTd[NC];
  __shared__ float    sTc[NC];
  int b = blockIdx.x;
  int Sn = d_Sn[b];
  int p0 = blockIdx.y*4;
  if (p0 >= Sn) return;
  int Tn = d_Tn[b];
  for (int q=threadIdx.x; q<Tn; q+=blockDim.x){
    int j = d_Tl[b*NC+q];
    sTi[q] = j; sTd[q] = d_dmask[b*NC+j];
    sTc[q] = rsqrtf(fmaxf(d_colsum[b*NC+j], EPSF));
  }
  __syncthreads();
  int d = threadIdx.x;
  int ii[4]; unsigned sm[4]; float acc[4];
  #pragma unroll
  for (int r=0;r<4;r++){
    int p = p0 + r;
    ii[r] = (p < Sn) ? d_Sl[b*NC+p] : -1;
    sm[r] = (p < Sn) ? d_smask[b*NC+ii[r]] : 0u;
    acc[r] = 0.f;
  }
  for (int q=0; q<Tn; q++){
    unsigned td = sTd[q]; int j = sTi[q];
    bool h0 = (sm[0] & td) && (j != ii[0]);
    bool h1 = (sm[1] & td) && (j != ii[1]);
    bool h2 = (sm[2] & td) && (j != ii[2]);
    bool h3 = (sm[3] & td) && (j != ii[3]);
    if (h0|h1|h2|h3){
      float v = sTc[q] * d_EWc[(size_t)j*HD + d];
      if (h0) acc[0] += v;
      if (h1) acc[1] += v;
      if (h2) acc[2] += v;
      if (h3) acc[3] += v;
    }
  }
  #pragma unroll
  for (int r=0;r<4;r++){
    int p = p0 + r;
    if (p < Sn){
      float rinv = rsqrtf(fmaxf(d_rowsum[b*NC+ii[r]], EPSF));
      d_yw[((size_t)b*NC + p)*HD + d] = rinv*acc[r];
    }
  }
}

// -------- pass2 (4 T-rows/block): zr[j] = relu(cinv_j * sum_i rinv_i*yw[i] + b_c)
__global__ void k_pass2(const float* __restrict__ b_c){
  __shared__ int      sSi[NC];
  __shared__ unsigned sSs[NC];
  __shared__ float    sSr[NC];
  int b = blockIdx.x;
  int Tn = d_Tn[b];
  int q0 = blockIdx.y*4;
  if (q0 >= Tn) return;
  int Sn = d_Sn[b];
  for (int p=threadIdx.x; p<Sn; p+=blockDim.x){
    int i = d_Sl[b*NC+p];
    sSi[p] = i; sSs[p] = d_smask[b*NC+i];
    sSr[p] = rsqrtf(fmaxf(d_rowsum[b*NC+i], EPSF));
  }
  __syncthreads();
  int d = threadIdx.x;
  int jj[4]; unsigned dm[4]; float acc[4];
  #pragma unroll
  for (int r=0;r<4;r++){
    int q = q0 + r;
    jj[r] = (q < Tn) ? d_Tl[b*NC+q] : -1;
    dm[r] = (q < Tn) ? d_dmask[b*NC+jj[r]] : 0u;
    acc[r] = 0.f;
  }
  for (int p=0; p<Sn; p++){
    unsigned ss = sSs[p]; int i = sSi[p];
    bool h0 = (ss & dm[0]) && (i != jj[0]);
    bool h1 = (ss & dm[1]) && (i != jj[1]);
    bool h2 = (ss & dm[2]) && (i != jj[2]);
    bool h3 = (ss & dm[3]) && (i != jj[3]);
    if (h0|h1|h2|h3){
      float v = sSr[p] * d_yw[((size_t)b*NC + p)*HD + d];
      if (h0) acc[0] += v;
      if (h1) acc[1] += v;
      if (h2) acc[2] += v;
      if (h3) acc[3] += v;
    }
  }
  float bc = b_c[d];
  #pragma unroll
  for (int r=0;r<4;r++){
    int q = q0 + r;
    if (q < Tn){
      float cinv = rsqrtf(fmaxf(d_colsum[b*NC+jj[r]], EPSF));
      d_zr[((size_t)b*NC + q)*HD + d] = fmaxf(cinv*acc[r] + bc, 0.f);
    }
  }
}

// -------- pooled partials over 8 deterministic chunks ----------------------------
__global__ void k_poolpart(const float* __restrict__ b_h, const float* __restrict__ b_i){
  int b = blockIdx.x, ch = blockIdx.y, d = threadIdx.x;
  int actn = d_actn[b], Tn = d_Tn[b];
  float bh = b_h[d], bi = b_i[d];
  float ah = 0.f, ai = 0.f;
  for (int p=ch; p<actn; p+=PCH){
    int i = d_act[b*NC+p];
    unsigned m = d_vmask[b*NC+i];
    float w = d_Dvinv[b*NC+i];
    float sh=0.f, si=0.f;
    while (m){
      int e = __ffs(m) - 1; m &= (m-1u);
      sh += d_tph[((size_t)b*EV+e)*HD + d];
      si += d_tpi[((size_t)b*EV+e)*HD + d];
    }
    ah += fmaxf(w*sh + bh, 0.f);
    ai += fmaxf(w*si + bi, 0.f);
  }
  float ac = 0.f;
  for (int q=ch; q<Tn; q+=PCH) ac += d_zr[((size_t)b*NC + q)*HD + d];
  float* pp = d_pp + ((size_t)(b*PCH + ch)*3)*HD;
  pp[0*HD+d] = ah;
  pp[1*HD+d] = ac;
  pp[2*HD+d] = ai;
}

__global__ void k_poolfin(const float* __restrict__ b_c){
  int b = blockIdx.x, d = threadIdx.x;
  int actn = d_actn[b], Tn = d_Tn[b];
  float ah=0.f, ac=0.f, ai=0.f;
  for (int ch=0; ch<PCH; ch++){
    const float* pp = d_pp + ((size_t)(b*PCH + ch)*3)*HD;
    ah += pp[0*HD+d];
    ac += pp[1*HD+d];
    ai += pp[2*HD+d];
  }
  ac += (float)(actn - Tn) * fmaxf(b_c[d], 0.f);
  float denom = fmaxf((float)actn, 1.f);
  d_eh[b*HD+d] = ah/denom;
  d_ec[b*HD+d] = ac/denom;
  d_ei[b*HD+d] = ai/denom;
}

// -------- gated residual -----------------------------------------------------------
__global__ void k_gates(const float* gwh, const float* gbh, const float* gwc,
                        const float* gbc, const float* gwi, const float* gbi){
  __shared__ float sr[HD];
  int b = blockIdx.x, d = threadIdx.x;
  float eh = d_eh[b*HD+d], ec = d_ec[b*HD+d], ei = d_ei[b*HD+d];
  float sh, sc, si;
  sr[d] = eh*gwh[d]; __syncthreads();
  for (int s=HD/2; s>0; s>>=1){ if (d<s) sr[d]+=sr[d+s]; __syncthreads(); }
  sh = sr[0]; __syncthreads();
  sr[d] = ec*gwc[d]; __syncthreads();
  for (int s=HD/2; s>0; s>>=1){ if (d<s) sr[d]+=sr[d+s]; __syncthreads(); }
  sc = sr[0]; __syncthreads();
  sr[d] = ei*gwi[d]; __syncthreads();
  for (int s=HD/2; s>0; s>>=1){ if (d<s) sr[d]+=sr[d+s]; __syncthreads(); }
  si = sr[0];
  float gh = 1.f/(1.f+expf(-(sh+gbh[0])));
  float gc = 1.f/(1.f+expf(-(sc+gbc[0])));
  float gi = 1.f/(1.f+expf(-(si+gbi[0])));
  d_res[b*HD+d] = gh*eh + gc*ec + gi*ei;
}

// -------- classifier ---------------------------------------------------------------
__global__ void k_cls(const float* __restrict__ Wc, const float* __restrict__ bc,
                      float* __restrict__ out){
  __shared__ float sres[HD];
  int b = blockIdx.x;
  int o = blockIdx.y*blockDim.x + threadIdx.x;
  for (int t=threadIdx.x; t<HD; t+=blockDim.x) sres[t] = d_res[b*HD+t];
  __syncthreads();
  if (o < NOUT){
    float acc = bc[o];
    for (int k=0; k<HD; k++) acc += sres[k]*Wc[(size_t)k*NOUT + o];
    out[(size_t)b*NOUT + o] = acc;
  }
}

// -------- InfoNCE loss (single block) ----------------------------------------------
__global__ void k_nce(float* __restrict__ out, int out_size){
  __shared__ float snorm[48];
  __shared__ float sE[256];
  int tid = threadIdx.x, wid = tid>>5, lane = tid&31;
  for (int row=wid; row<48; row+=8){
    const float* base = (row<16) ? (d_eh + row*HD)
                      : (row<32) ? (d_ec + (row-16)*HD)
                                 : (d_ei + (row-32)*HD);
    float s = 0.f;
    for (int d=lane; d<HD; d+=32){ float v = base[d]; s += v*v; }
    s = warp_sum(s);
    if (lane==0) snorm[row] = fmaxf(sqrtf(s), EPSF);
  }
  __syncthreads();
  float total = 0.f;
  for (int pair=0; pair<2; pair++){
    const float* Bm = pair ? d_ei : d_ec;
    int boff = pair ? 32 : 16;
    for (int idx=wid; idx<256; idx+=8){
      int i = idx>>4, j = idx&15;
      const float* a  = d_eh + i*HD;
      const float* bb = Bm   + j*HD;
      float s = 0.f;
      for (int d=lane; d<HD; d+=32) s += a[d]*bb[d];
      s = warp_sum(s);
      if (lane==0) sE[idx] = expf(s / (snorm[i]*snorm[boff+j]*0.4f));
    }
    __syncthreads();
    if (tid==0){
      float l = 0.f;
      for (int i=0;i<16;i++){
        float neg = 0.f;
        for (int j=0;j<16;j++) neg += sE[i*16+j];
        float pos = sE[i*16+i];
        l += -logf(pos/(neg + 1e-8f) + 1e-8f);
      }
      total += l/16.f;
    }
    __syncthreads();
  }
  if (tid==0 && out_size > NB*NOUT) out[NB*NOUT] = total;
}

// ==================================================================================
extern "C" void kernel_launch(void* const* d_in, const int* in_sizes, int n_in,
                              void* d_out, int out_size){
  (void)in_sizes; (void)n_in;
  const float* code_x = (const float*)d_in[0];
  const int*   lens   = (const int*)  d_in[1];
  const float* emb    = (const float*)d_in[2];
  const float* adj    = (const float*)d_in[3];
  const float* ln_g   = (const float*)d_in[4];
  const float* ln_b   = (const float*)d_in[5];
  const float* W_h    = (const float*)d_in[6];
  const float* b_h    = (const float*)d_in[7];
  const float* W_c    = (const float*)d_in[8];
  const float* b_c    = (const float*)d_in[9];
  const float* W_i    = (const float*)d_in[10];
  const float* b_i    = (const float*)d_in[11];
  const float* gw_h   = (const float*)d_in[12];
  const float* gb_h   = (const float*)d_in[13];
  const float* gw_c   = (const float*)d_in[14];
  const float* gb_c   = (const float*)d_in[15];
  const float* gw_i   = (const float*)d_in[16];
  const float* gb_i   = (const float*)d_in[17];
  const float* W_cls  = (const float*)d_in[18];
  const float* b_cls  = (const float*)d_in[19];
  float* out = (float*)d_out;

  // sparse structure of adj (binary -> index-only)
  k_csr_rows<<<(NC + 31)/32, 1024>>>(adj);
  kA_colcount<<<dim3(NCHUNK, (NC+255)/256), 256>>>(adj);
  kB_colprefix<<<(NC+255)/256, 256>>>();
  kC_colfill<<<dim3(NCHUNK, (NC+255)/256), 256>>>(adj);

  // per-patient masks (also zeroes colsum) -- overlaps with icd stream work
  k_masks<<<dim3(NB, (NC+255)/256), 256>>>(code_x, lens);

  // icd_conv: 3x [ adj.T @ (adj @ x) -> LN ]
  k_spmm_rows<<<NC, DD>>>(emb, 0);
  k_spmm_cols_ln<<<NC, DD>>>(ln_g, ln_b);
  k_spmm_rows<<<NC, DD>>>(emb, 1);
  k_spmm_cols_ln<<<NC, DD>>>(ln_g, ln_b);
  k_spmm_rows<<<NC, DD>>>(emb, 1);
  k_spmm_cols_ln<<<NC, DD>>>(ln_g, ln_b);

  // precompute X @ W for the three branches
  k_gemm<<<NC/16, 256>>>(emb, W_h, 0);
  k_gemm<<<NC/16, 256>>>(emb, W_c, 1);
  k_gemm<<<NC/16, 256>>>(emb, W_i, 2);   // uses d_icd internally

  k_compact<<<NB, 1024>>>();
  k_tprime<<<dim3(NB, EV), HD>>>();
  k_rowcol<<<dim3(NB, 8), 256>>>();
  k_pass1<<<dim3(NB, (NC+3)/4), HD>>>();
  k_pass2<<<dim3(NB, (NC+3)/4), HD>>>(b_c);
  k_poolpart<<<dim3(NB, PCH), HD>>>(b_h, b_i);
  k_poolfin<<<NB, HD>>>(b_c);
  k_gates<<<NB, HD>>>(gw_h, gb_h, gw_c, gb_c, gw_i, gb_i);
  k_cls<<<dim3(NB, (NOUT + 255)/256), 256>>>(W_cls, b_cls, out);
  k_nce<<<1, 256>>>(out, out_size);
}

// round 3
// speedup vs baseline: 3.3182x; 3.3182x over previous
#include <cuda_runtime.h>
#include <math.h>

#define NC   2000   // codes
#define EV   32     // visits
#define DD   128    // embedding dim
#define HD   256    // hidden dim
#define NOUT 1000
#define NB   16     // batch
#define PAD  128    // max nnz per adj row/col
#define VCAP 128    // max codes per visit
#define NCHUNK 40   // CSC build chunks (40 x 50 rows)
#define CHROWS 50
#define PCH  8      // pool partial chunks
#define RPB  8      // rows per block in pass kernels
#define QT   512    // hit-list tile size
#define EPSF 1e-12f

// ---------------- scratch (device globals; no allocation) ----------------
static __device__ float d_icd[NC*DD];
static __device__ float d_buf[NC*DD];
static __device__ float d_EWh[NC*HD];
static __device__ float d_EWc[NC*HD];
static __device__ float d_IWi[NC*HD];

static __device__ int   d_rowcnt[NC];
static __device__ int   d_rowidx[NC*PAD];
static __device__ int   d_colcnt[NC];
static __device__ int   d_colidx[NC*PAD];
static __device__ int   d_coff[NCHUNK*NC];

static __device__ unsigned d_vmask[NB*NC];
static __device__ unsigned d_smask[NB*NC];
static __device__ unsigned d_dmask[NB*NC];
static __device__ float d_Dv[NB*NC];
static __device__ float d_Dvinv[NB*NC];
static __device__ int d_act[NB*NC];  static __device__ int d_actn[NB];
static __device__ int d_Sl[NB*NC];   static __device__ int d_Sn[NB];
static __device__ int d_Tl[NB*NC];   static __device__ int d_Tn[NB];
static __device__ int d_vl[NB*EV*VCAP];
static __device__ int d_vlen[NB*EV];
static __device__ float d_rowsum[NB*NC];
static __device__ float d_colsum[NB*NC];
static __device__ float d_tph[NB*EV*HD];
static __device__ float d_tpi[NB*EV*HD];
static __device__ float d_yw[(size_t)NB*NC*HD];  // A @ (emb@W_c), rows by S-position
static __device__ float d_zr[(size_t)NB*NC*HD];  // relu(A^T @ yw + b_c), rows by T-position
static __device__ float d_pp[NB*PCH*3*HD];
static __device__ float d_eh[NB*HD], d_ec[NB*HD], d_ei[NB*HD];
static __device__ float d_res[NB*HD];

__device__ __forceinline__ float warp_sum(float v){
  #pragma unroll
  for (int o=16;o>0;o>>=1) v += __shfl_down_sync(0xffffffffu, v, o);
  return v;
}

// ---------------- CSR of adj (warp per row, deterministic ascending) ----------
__global__ void k_csr_rows(const float* __restrict__ adj){
  int w = threadIdx.x >> 5, lane = threadIdx.x & 31;
  int r = blockIdx.x*32 + w;
  if (r >= NC) return;
  int cnt = 0;
  for (int jt=0; jt<NC; jt+=32){
    int j = jt + lane;
    float v = (j < NC) ? adj[(size_t)r*NC + j] : 0.f;
    unsigned m = __ballot_sync(0xffffffffu, v != 0.f);
    if (v != 0.f){
      int pos = cnt + __popc(m & ((1u<<lane)-1u));
      if (pos < PAD) d_rowidx[r*PAD+pos] = j;
    }
    cnt += __popc(m);
  }
  if (lane == 0) d_rowcnt[r] = (cnt < PAD) ? cnt : PAD;
}

// ---------------- CSC build: 3-phase deterministic chunked --------------------
__global__ void kA_colcount(const float* __restrict__ adj){
  int j = blockIdx.y*blockDim.x + threadIdx.x;
  if (j >= NC) return;
  int c = blockIdx.x;
  int cnt = 0;
  int i0 = c*CHROWS;
  for (int i=i0; i<i0+CHROWS; i++)
    if (adj[(size_t)i*NC + j] != 0.f) cnt++;
  d_coff[c*NC + j] = cnt;
}
__global__ void kB_colprefix(){
  int j = blockIdx.x*blockDim.x + threadIdx.x;
  if (j >= NC) return;
  int run = 0;
  for (int c=0; c<NCHUNK; c++){
    int v = d_coff[c*NC + j];
    d_coff[c*NC + j] = run;
    run += v;
  }
  d_colcnt[j] = (run < PAD) ? run : PAD;
}
__global__ void kC_colfill(const float* __restrict__ adj){
  int j = blockIdx.y*blockDim.x + threadIdx.x;
  if (j >= NC) return;
  int c = blockIdx.x;
  int pos = d_coff[c*NC + j];
  int i0 = c*CHROWS;
  for (int i=i0; i<i0+CHROWS; i++){
    if (adj[(size_t)i*NC + j] != 0.f){
      if (pos < PAD) d_colidx[j*PAD + pos] = i;
      pos++;
    }
  }
}

// ---------------- sparse y = adj @ x (binary adj -> plain gather-sum) -----------
__global__ void k_spmm_rows(const float* __restrict__ emb, int use_icd){
  const float* src = use_icd ? d_icd : emb;
  int i = blockIdx.x, d = threadIdx.x;
  int cnt = d_rowcnt[i];
  const int* idx = d_rowidx + i*PAD;
  float acc = 0.f;
  for (int p=0; p<cnt; p++) acc += src[(size_t)idx[p]*DD + d];
  d_buf[i*DD + d] = acc;
}

// ---------------- x = LN(adj.T @ buf) -------------------------------------------
__global__ void k_spmm_cols_ln(const float* __restrict__ g, const float* __restrict__ b){
  int j = blockIdx.x, d = threadIdx.x;
  int cnt = d_colcnt[j];
  const int* idx = d_colidx + j*PAD;
  float acc = 0.f;
  for (int p=0; p<cnt; p++) acc += d_buf[(size_t)idx[p]*DD + d];
  __shared__ float sred[DD];
  sred[d] = acc; __syncthreads();
  for (int s=DD/2; s>0; s>>=1){ if (d < s) sred[d] += sred[d+s]; __syncthreads(); }
  float m = sred[0]/(float)DD; __syncthreads();
  float diff = acc - m;
  sred[d] = diff*diff; __syncthreads();
  for (int s=DD/2; s>0; s>>=1){ if (d < s) sred[d] += sred[d+s]; __syncthreads(); }
  float var = sred[0]/(float)DD;
  d_icd[j*DD + d] = diff*rsqrtf(var + 1e-5f)*g[d] + b[d];
}

// ---------------- EW = X @ W (tiled, 16 rows per block) --------------------------
__global__ void k_gemm(const float* __restrict__ Xin, const float* __restrict__ W, int which){
  const float* X = (which == 2) ? d_icd : Xin;
  float* O = (which == 0) ? d_EWh : (which == 1) ? d_EWc : d_IWi;
  __shared__ float xs[16][DD];
  int r0 = blockIdx.x*16;
  for (int t=threadIdx.x; t<16*DD; t+=256)
    xs[t/DD][t%DD] = X[(size_t)(r0 + t/DD)*DD + (t%DD)];
  __syncthreads();
  float acc[16];
  #pragma unroll
  for (int r=0;r<16;r++) acc[r]=0.f;
  for (int k=0; k<DD; k++){
    float w = W[(size_t)k*HD + threadIdx.x];
    #pragma unroll
    for (int r=0;r<16;r++) acc[r] += xs[r][k]*w;
  }
  #pragma unroll
  for (int r=0;r<16;r++) O[(size_t)(r0+r)*HD + threadIdx.x] = acc[r];
}

// ---------------- per-patient masks / degrees (parallel over code chunks) -------
__global__ void k_masks(const float* __restrict__ cx, const int* __restrict__ lens){
  int b = blockIdx.x;
  int i = blockIdx.y*blockDim.x + threadIdx.x;
  if (i >= NC) return;
  int len = lens[b];
  const float* cxb = cx + (size_t)b*EV*NC;
  unsigned m = 0; int c = 0;
  for (int e=0; e<len; e++){
    if (cxb[(size_t)e*NC + i] != 0.f){ m |= (1u<<e); c++; }
  }
  d_vmask[b*NC+i] = m;
  d_Dv[b*NC+i]    = (float)c;
  d_Dvinv[b*NC+i] = rsqrtf(fmaxf((float)c, EPSF));
  unsigned lowm = (1u << (len-1)) - 1u;
  d_smask[b*NC+i] = m & lowm;
  d_dmask[b*NC+i] = (m >> 1) & lowm;
}

// ---------------- compact lists: per-visit (32 warps) + act/S/T (3 warps) -------
__global__ void k_compact(){
  int b = blockIdx.x;
  int w = threadIdx.x >> 5, lane = threadIdx.x & 31;
  unsigned ltm = (1u<<lane)-1u;
  {
    int cnt = 0;
    for (int base=0; base<NC; base+=32){
      int i = base + lane;
      bool v = (i<NC) && ((d_vmask[b*NC+i] >> w) & 1u);
      unsigned mm = __ballot_sync(0xffffffffu, v);
      if (v){
        int pos = cnt + __popc(mm & ltm);
        if (pos < VCAP) d_vl[((size_t)b*EV + w)*VCAP + pos] = i;
      }
      cnt += __popc(mm);
    }
    if (lane == 0) d_vlen[b*EV + w] = (cnt < VCAP) ? cnt : VCAP;
  }
  if (w < 3){
    int cnt = 0;
    int* dst = (w==0) ? (d_act + b*NC) : (w==1) ? (d_Sl + b*NC) : (d_Tl + b*NC);
    for (int base=0; base<NC; base+=32){
      int i = base + lane;
      bool v;
      if (w==0)      v = (i<NC) && (d_Dv[b*NC+i] > 0.f);
      else if (w==1) v = (i<NC) && (d_smask[b*NC+i] != 0u);
      else           v = (i<NC) && (d_dmask[b*NC+i] != 0u);
      unsigned mm = __ballot_sync(0xffffffffu, v);
      if (v) dst[cnt + __popc(mm & ltm)] = i;
      cnt += __popc(mm);
    }
    if (lane == 0){
      if (w==0) d_actn[b]=cnt; else if (w==1) d_Sn[b]=cnt; else d_Tn[b]=cnt;
    }
  }
}

// -------- t'[e] = invDe * sum_{i in visit e} Dvinv_i * (X@W)[i] -------------------
__global__ void k_tprime(){
  int b = blockIdx.x, e = blockIdx.y, d = threadIdx.x;
  int n = d_vlen[b*EV + e];
  const int* vl = d_vl + ((size_t)b*EV + e)*VCAP;
  float acch = 0.f, acci = 0.f;
  for (int k=0; k<n; k++){
    int i = vl[k];
    float w = d_Dvinv[b*NC+i];
    acch += w * d_EWh[(size_t)i*HD + d];
    acci += w * d_IWi[(size_t)i*HD + d];
  }
  float inv = 1.f / fmaxf((float)n, EPSF);
  d_tph[((size_t)b*EV+e)*HD + d] = acch*inv;
  d_tpi[((size_t)b*EV+e)*HD + d] = acci*inv;
}

// -------- row & col degree sums of A, atomic-free (z=0: rowsum, z=1: colsum) ----
__global__ void k_degrees(){
  __shared__ int      sIdx[NC];
  __shared__ unsigned sMsk[NC];
  int b = blockIdx.x, z = blockIdx.z;
  int Rn = z ? d_Tn[b] : d_Sn[b];
  int Cn = z ? d_Sn[b] : d_Tn[b];
  const int* rl = z ? (d_Tl + b*NC) : (d_Sl + b*NC);
  const int* cl = z ? (d_Sl + b*NC) : (d_Tl + b*NC);
  for (int q=threadIdx.x; q<Cn; q+=blockDim.x){
    int j = cl[q];
    sIdx[q] = j;
    sMsk[q] = z ? d_smask[b*NC+j] : d_dmask[b*NC+j];
  }
  __syncthreads();
  for (int p = blockIdx.y*blockDim.x + threadIdx.x; p < Rn; p += gridDim.y*blockDim.x){
    int i = rl[p];
    unsigned m = z ? d_dmask[b*NC+i] : d_smask[b*NC+i];
    float s = 0.f;
    for (int q=0; q<Cn; q++)
      s += ((m & sMsk[q]) && (sIdx[q] != i)) ? 1.f : 0.f;
    if (z) d_colsum[b*NC+i] = s; else d_rowsum[b*NC+i] = s;
  }
}

// -------- pass1 (8 S-rows/block, warp-built hit lists) ---------------------------
__global__ void k_pass1(){
  __shared__ int      sTi[NC];
  __shared__ unsigned sTd[NC];
  __shared__ float    sTc[NC];
  __shared__ unsigned short hl[RPB][QT];
  __shared__ int      hn[RPB];
  int b = blockIdx.x;
  int Sn = d_Sn[b];
  int p0 = blockIdx.y*RPB;
  if (p0 >= Sn) return;
  int Tn = d_Tn[b];
  int tid = threadIdx.x, w = tid>>5, lane = tid&31;
  unsigned ltm = (1u<<lane)-1u;
  for (int q=tid; q<Tn; q+=256){
    int j = d_Tl[b*NC+q];
    sTi[q] = j; sTd[q] = d_dmask[b*NC+j];
    sTc[q] = rsqrtf(fmaxf(d_colsum[b*NC+j], EPSF));
  }
  int nr = Sn - p0; if (nr > RPB) nr = RPB;
  int ii_w = 0; unsigned sm_w = 0;
  if (w < nr){ ii_w = d_Sl[b*NC+p0+w]; sm_w = d_smask[b*NC+ii_w]; }
  float acc[RPB];
  #pragma unroll
  for (int r=0;r<RPB;r++) acc[r]=0.f;
  int d = tid;
  __syncthreads();
  for (int q0=0; q0<Tn; q0+=QT){
    int qe = q0+QT; if (qe > Tn) qe = Tn;
    if (w < nr){
      int cnt = 0;
      int iters = (qe - q0 + 31) >> 5;
      for (int it=0; it<iters; it++){
        int q = q0 + it*32 + lane;
        bool hit = (q < qe) && (sm_w & sTd[q]) && (sTi[q] != ii_w);
        unsigned mm = __ballot_sync(0xffffffffu, hit);
        if (hit) hl[w][cnt + __popc(mm & ltm)] = (unsigned short)q;
        cnt += __popc(mm);
      }
      if (lane == 0) hn[w] = cnt;
    }
    __syncthreads();
    #pragma unroll
    for (int r=0; r<RPB; r++){
      if (r >= nr) break;
      int n = hn[r];
      for (int k=0; k<n; k++){
        int q = hl[r][k];
        acc[r] += sTc[q] * d_EWc[(size_t)sTi[q]*HD + d];
      }
    }
    __syncthreads();
  }
  #pragma unroll
  for (int r=0; r<RPB; r++){
    if (r >= nr) break;
    int p = p0 + r;
    int i = d_Sl[b*NC+p];
    float rinv = rsqrtf(fmaxf(d_rowsum[b*NC+i], EPSF));
    d_yw[((size_t)b*NC + p)*HD + d] = rinv*acc[r];
  }
}

// -------- pass2 (8 T-rows/block, warp-built hit lists) ---------------------------
__global__ void k_pass2(const float* __restrict__ b_c){
  __shared__ int      sSi[NC];
  __shared__ unsigned sSs[NC];
  __shared__ float    sSr[NC];
  __shared__ unsigned short hl[RPB][QT];
  __shared__ int      hn[RPB];
  int b = blockIdx.x;
  int Tn = d_Tn[b];
  int q0b = blockIdx.y*RPB;
  if (q0b >= Tn) return;
  int Sn = d_Sn[b];
  int tid = threadIdx.x, w = tid>>5, lane = tid&31;
  unsigned ltm = (1u<<lane)-1u;
  for (int p=tid; p<Sn; p+=256){
    int i = d_Sl[b*NC+p];
    sSi[p] = i; sSs[p] = d_smask[b*NC+i];
    sSr[p] = rsqrtf(fmaxf(d_rowsum[b*NC+i], EPSF));
  }
  int nr = Tn - q0b; if (nr > RPB) nr = RPB;
  int jj_w = 0; unsigned dm_w = 0;
  if (w < nr){ jj_w = d_Tl[b*NC+q0b+w]; dm_w = d_dmask[b*NC+jj_w]; }
  float acc[RPB];
  #pragma unroll
  for (int r=0;r<RPB;r++) acc[r]=0.f;
  int d = tid;
  __syncthreads();
  for (int p0=0; p0<Sn; p0+=QT){
    int pe = p0+QT; if (pe > Sn) pe = Sn;
    if (w < nr){
      int cnt = 0;
      int iters = (pe - p0 + 31) >> 5;
      for (int it=0; it<iters; it++){
        int p = p0 + it*32 + lane;
        bool hit = (p < pe) && (dm_w & sSs[p]) && (sSi[p] != jj_w);
        unsigned mm = __ballot_sync(0xffffffffu, hit);
        if (hit) hl[w][cnt + __popc(mm & ltm)] = (unsigned short)p;
        cnt += __popc(mm);
      }
      if (lane == 0) hn[w] = cnt;
    }
    __syncthreads();
    #pragma unroll
    for (int r=0; r<RPB; r++){
      if (r >= nr) break;
      int n = hn[r];
      for (int k=0; k<n; k++){
        int p = hl[r][k];
        acc[r] += sSr[p] * d_yw[((size_t)b*NC + p)*HD + d];
      }
    }
    __syncthreads();
  }
  float bc = b_c[d];
  #pragma unroll
  for (int r=0; r<RPB; r++){
    if (r >= nr) break;
    int q = q0b + r;
    int j = d_Tl[b*NC+q];
    float cinv = rsqrtf(fmaxf(d_colsum[b*NC+j], EPSF));
    d_zr[((size_t)b*NC + q)*HD + d] = fmaxf(cinv*acc[r] + bc, 0.f);
  }
}

// -------- pooled partials over 8 deterministic chunks ----------------------------
__global__ void k_poolpart(const float* __restrict__ b_h, const float* __restrict__ b_i){
  int b = blockIdx.x, ch = blockIdx.y, d = threadIdx.x;
  int actn = d_actn[b], Tn = d_Tn[b];
  float bh = b_h[d], bi = b_i[d];
  float ah = 0.f, ai = 0.f;
  for (int p=ch; p<actn; p+=PCH){
    int i = d_act[b*NC+p];
    unsigned m = d_vmask[b*NC+i];
    float w = d_Dvinv[b*NC+i];
    float sh=0.f, si=0.f;
    while (m){
      int e = __ffs(m) - 1; m &= (m-1u);
      sh += d_tph[((size_t)b*EV+e)*HD + d];
      si += d_tpi[((size_t)b*EV+e)*HD + d];
    }
    ah += fmaxf(w*sh + bh, 0.f);
    ai += fmaxf(w*si + bi, 0.f);
  }
  float ac = 0.f;
  for (int q=ch; q<Tn; q+=PCH) ac += d_zr[((size_t)b*NC + q)*HD + d];
  float* pp = d_pp + ((size_t)(b*PCH + ch)*3)*HD;
  pp[0*HD+d] = ah;
  pp[1*HD+d] = ac;
  pp[2*HD+d] = ai;
}

__global__ void k_poolfin(const float* __restrict__ b_c){
  int b = blockIdx.x, d = threadIdx.x;
  int actn = d_actn[b], Tn = d_Tn[b];
  float ah=0.f, ac=0.f, ai=0.f;
  for (int ch=0; ch<PCH; ch++){
    const float* pp = d_pp + ((size_t)(b*PCH + ch)*3)*HD;
    ah += pp[0*HD+d];
    ac += pp[1*HD+d];
    ai += pp[2*HD+d];
  }
  ac += (float)(actn - Tn) * fmaxf(b_c[d], 0.f);
  float denom = fmaxf((float)actn, 1.f);
  d_eh[b*HD+d] = ah/denom;
  d_ec[b*HD+d] = ac/denom;
  d_ei[b*HD+d] = ai/denom;
}

// -------- gated residual -----------------------------------------------------------
__global__ void k_gates(const float* gwh, const float* gbh, const float* gwc,
                        const float* gbc, const float* gwi, const float* gbi){
  __shared__ float sr[HD];
  int b = blockIdx.x, d = threadIdx.x;
  float eh = d_eh[b*HD+d], ec = d_ec[b*HD+d], ei = d_ei[b*HD+d];
  float sh, sc, si;
  sr[d] = eh*gwh[d]; __syncthreads();
  for (int s=HD/2; s>0; s>>=1){ if (d<s) sr[d]+=sr[d+s]; __syncthreads(); }
  sh = sr[0]; __syncthreads();
  sr[d] = ec*gwc[d]; __syncthreads();
  for (int s=HD/2; s>0; s>>=1){ if (d<s) sr[d]+=sr[d+s]; __syncthreads(); }
  sc = sr[0]; __syncthreads();
  sr[d] = ei*gwi[d]; __syncthreads();
  for (int s=HD/2; s>0; s>>=1){ if (d<s) sr[d]+=sr[d+s]; __syncthreads(); }
  si = sr[0];
  float gh = 1.f/(1.f+expf(-(sh+gbh[0])));
  float gc = 1.f/(1.f+expf(-(sc+gbc[0])));
  float gi = 1.f/(1.f+expf(-(si+gbi[0])));
  d_res[b*HD+d] = gh*eh + gc*ec + gi*ei;
}

// -------- classifier ---------------------------------------------------------------
__global__ void k_cls(const float* __restrict__ Wc, const float* __restrict__ bc,
                      float* __restrict__ out){
  __shared__ float sres[HD];
  int b = blockIdx.x;
  int o = blockIdx.y*blockDim.x + threadIdx.x;
  for (int t=threadIdx.x; t<HD; t+=blockDim.x) sres[t] = d_res[b*HD+t];
  __syncthreads();
  if (o < NOUT){
    float acc = bc[o];
    for (int k=0; k<HD; k++) acc += sres[k]*Wc[(size_t)k*NOUT + o];
    out[(size_t)b*NOUT + o] = acc;
  }
}

// -------- InfoNCE loss (single block) ----------------------------------------------
__global__ void k_nce(float* __restrict__ out, int out_size){
  __shared__ float snorm[48];
  __shared__ float sE[256];
  int tid = threadIdx.x, wid = tid>>5, lane = tid&31;
  for (int row=wid; row<48; row+=8){
    const float* base = (row<16) ? (d_eh + row*HD)
                      : (row<32) ? (d_ec + (row-16)*HD)
                                 : (d_ei + (row-32)*HD);
    float s = 0.f;
    for (int d=lane; d<HD; d+=32){ float v = base[d]; s += v*v; }
    s = warp_sum(s);
    if (lane==0) snorm[row] = fmaxf(sqrtf(s), EPSF);
  }
  __syncthreads();
  float total = 0.f;
  for (int pair=0; pair<2; pair++){
    const float* Bm = pair ? d_ei : d_ec;
    int boff = pair ? 32 : 16;
    for (int idx=wid; idx<256; idx+=8){
      int i = idx>>4, j = idx&15;
      const float* a  = d_eh + i*HD;
      const float* bb = Bm   + j*HD;
      float s = 0.f;
      for (int d=lane; d<HD; d+=32) s += a[d]*bb[d];
      s = warp_sum(s);
      if (lane==0) sE[idx] = expf(s / (snorm[i]*snorm[boff+j]*0.4f));
    }
    __syncthreads();
    if (tid==0){
      float l = 0.f;
      for (int i=0;i<16;i++){
        float neg = 0.f;
        for (int j=0;j<16;j++) neg += sE[i*16+j];
        float pos = sE[i*16+i];
        l += -logf(pos/(neg + 1e-8f) + 1e-8f);
      }
      total += l/16.f;
    }
    __syncthreads();
  }
  if (tid==0 && out_size > NB*NOUT) out[NB*NOUT] = total;
}

// ==================================================================================
extern "C" void kernel_launch(void* const* d_in, const int* in_sizes, int n_in,
                              void* d_out, int out_size){
  (void)in_sizes; (void)n_in;
  const float* code_x = (const float*)d_in[0];
  const int*   lens   = (const int*)  d_in[1];
  const float* emb    = (const float*)d_in[2];
  const float* adj    = (const float*)d_in[3];
  const float* ln_g   = (const float*)d_in[4];
  const float* ln_b   = (const float*)d_in[5];
  const float* W_h    = (const float*)d_in[6];
  const float* b_h    = (const float*)d_in[7];
  const float* W_c    = (const float*)d_in[8];
  const float* b_c    = (const float*)d_in[9];
  const float* W_i    = (const float*)d_in[10];
  const float* b_i    = (const float*)d_in[11];
  const float* gw_h   = (const float*)d_in[12];
  const float* gb_h   = (const float*)d_in[13];
  const float* gw_c   = (const float*)d_in[14];
  const float* gb_c   = (const float*)d_in[15];
  const float* gw_i   = (const float*)d_in[16];
  const float* gb_i   = (const float*)d_in[17];
  const float* W_cls  = (const float*)d_in[18];
  const float* b_cls  = (const float*)d_in[19];
  float* out = (float*)d_out;

  // sparse structure of adj (binary -> index-only)
  k_csr_rows<<<(NC + 31)/32, 1024>>>(adj);
  kA_colcount<<<dim3(NCHUNK, (NC+255)/256), 256>>>(adj);
  kB_colprefix<<<(NC+255)/256, 256>>>();
  kC_colfill<<<dim3(NCHUNK, (NC+255)/256), 256>>>(adj);

  // per-patient masks
  k_masks<<<dim3(NB, (NC+255)/256), 256>>>(code_x, lens);

  // icd_conv: 3x [ adj.T @ (adj @ x) -> LN ]
  k_spmm_rows<<<NC, DD>>>(emb, 0);
  k_spmm_cols_ln<<<NC, DD>>>(ln_g, ln_b);
  k_spmm_rows<<<NC, DD>>>(emb, 1);
  k_spmm_cols_ln<<<NC, DD>>>(ln_g, ln_b);
  k_spmm_rows<<<NC, DD>>>(emb, 1);
  k_spmm_cols_ln<<<NC, DD>>>(ln_g, ln_b);

  // precompute X @ W for the three branches
  k_gemm<<<NC/16, 256>>>(emb, W_h, 0);
  k_gemm<<<NC/16, 256>>>(emb, W_c, 1);
  k_gemm<<<NC/16, 256>>>(emb, W_i, 2);   // uses d_icd internally

  k_compact<<<NB, 1024>>>();
  k_tprime<<<dim3(NB, EV), HD>>>();
  k_degrees<<<dim3(NB, 4, 2), 256>>>();
  k_pass1<<<dim3(NB, (NC + RPB - 1)/RPB), HD>>>();
  k_pass2<<<dim3(NB, (NC + RPB - 1)/RPB), HD>>>(b_c);
  k_poolpart<<<dim3(NB, PCH), HD>>>(b_h, b_i);
  k_poolfin<<<NB, HD>>>(b_c);
  k_gates<<<NB, HD>>>(gw_h, gb_h, gw_c, gb_c, gw_i, gb_i);
  k_cls<<<dim3(NB, (NOUT + 255)/256), 256>>>(W_cls, b_cls, out);
  k_nce<<<1, 256>>>(out, out_size);
}